// round 4
// baseline (speedup 1.0000x reference)
#include <cuda_runtime.h>
#include <math.h>

#define C_CLASSES 21
#define B_BATCH 8
#define HW (512 * 512)            // elements per (b,c) chunk
#define HW4 (HW / 4)              // 65536 float4 per chunk
#define NCHUNKS (B_BATCH * C_CLASSES)  // 168
#define BLOCKS_PER_CHUNK 32
#define THREADS 256
#define NBLOCKS (NCHUNKS * BLOCKS_PER_CHUNK)       // 5376
#define F4_PER_BLOCK (HW4 / BLOCKS_PER_CHUNK)      // 2048
#define F4_PER_THREAD (F4_PER_BLOCK / THREADS)     // 8

// scratch: [class][0]=inter, [1]=pred_sum, [2]=target_sum
// zero-initialized at module load; self-reset via atomicExch each run.
__device__ int g_counts[C_CLASSES * 3];
__device__ unsigned int g_done;

__global__ __launch_bounds__(THREADS) void jaccard_fused_kernel(
    const float* __restrict__ preds, const float* __restrict__ target,
    float* __restrict__ out) {
    int chunk = blockIdx.x / BLOCKS_PER_CHUNK;   // which (b,c)
    int sub   = blockIdx.x % BLOCKS_PER_CHUNK;
    int cls   = chunk % C_CLASSES;

    const float4* p = reinterpret_cast<const float4*>(preds)  + (size_t)chunk * HW4;
    const float4* t = reinterpret_cast<const float4*>(target) + (size_t)chunk * HW4;

    int base = sub * F4_PER_BLOCK + threadIdx.x;

    int inter = 0, ps = 0, ts = 0;
#pragma unroll
    for (int i = 0; i < F4_PER_THREAD; i++) {
        int idx = base + i * THREADS;
        float4 pv = p[idx];
        float4 tv = t[idx];
        int pm, tm;
        pm = pv.x >= 0.5f; tm = tv.x == 1.0f; ps += pm; ts += tm; inter += pm & tm;
        pm = pv.y >= 0.5f; tm = tv.y == 1.0f; ps += pm; ts += tm; inter += pm & tm;
        pm = pv.z >= 0.5f; tm = tv.z == 1.0f; ps += pm; ts += tm; inter += pm & tm;
        pm = pv.w >= 0.5f; tm = tv.w == 1.0f; ps += pm; ts += tm; inter += pm & tm;
    }

    // warp reduction
#pragma unroll
    for (int off = 16; off > 0; off >>= 1) {
        inter += __shfl_down_sync(0xFFFFFFFFu, inter, off);
        ps    += __shfl_down_sync(0xFFFFFFFFu, ps, off);
        ts    += __shfl_down_sync(0xFFFFFFFFu, ts, off);
    }

    __shared__ int s_inter[THREADS / 32];
    __shared__ int s_ps[THREADS / 32];
    __shared__ int s_ts[THREADS / 32];
    int lane = threadIdx.x & 31;
    int wid  = threadIdx.x >> 5;
    if (lane == 0) { s_inter[wid] = inter; s_ps[wid] = ps; s_ts[wid] = ts; }
    __syncthreads();

    if (threadIdx.x == 0) {
        int bi = 0, bp = 0, bt = 0;
#pragma unroll
        for (int w = 0; w < THREADS / 32; w++) { bi += s_inter[w]; bp += s_ps[w]; bt += s_ts[w]; }
        atomicAdd(&g_counts[cls * 3 + 0], bi);
        atomicAdd(&g_counts[cls * 3 + 1], bp);
        atomicAdd(&g_counts[cls * 3 + 2], bt);

        // completion protocol: last block finalizes + resets all state
        __threadfence();
        unsigned int old = atomicAdd(&g_done, 1u);
        if (old == NBLOCKS - 1) {
            // all blocks' atomics are globally visible (atomics serialize at L2,
            // and each block fenced before incrementing g_done)
#pragma unroll
            for (int c = 0; c < C_CLASSES; c++) {
                // atomicExch: coherent read + reset-to-zero for next graph replay
                float fi = (float)atomicExch(&g_counts[c * 3 + 0], 0);
                float fp = (float)atomicExch(&g_counts[c * 3 + 1], 0);
                float ft = (float)atomicExch(&g_counts[c * 3 + 2], 0);
                float uni = fp + ft - fi;
                float iou = fi / fmaxf(uni, 1.0f);
                out[c] = (uni == 0.0f) ? nanf("") : iou;
            }
            atomicExch(&g_done, 0u);   // reset for next replay
        }
    }
}

extern "C" void kernel_launch(void* const* d_in, const int* in_sizes, int n_in,
                              void* d_out, int out_size) {
    const float* preds  = (const float*)d_in[0];
    const float* target = (const float*)d_in[1];
    float* out = (float*)d_out;

    jaccard_fused_kernel<<<NBLOCKS, THREADS>>>(preds, target, out);
}

// round 9
// speedup vs baseline: 1.2380x; 1.2380x over previous
#include <cuda_runtime.h>
#include <math.h>

#define C_CLASSES 21
#define B_BATCH 8
#define HW (512 * 512)            // elements per (b,c) chunk
#define HW4 (HW / 4)              // 65536 float4 per chunk
#define NCHUNKS (B_BATCH * C_CLASSES)  // 168
#define BLOCKS_PER_CHUNK 32
#define THREADS 256
#define F4_PER_BLOCK (HW4 / BLOCKS_PER_CHUNK)      // 2048
#define F4_PER_THREAD (F4_PER_BLOCK / THREADS)     // 8

// scratch: [class][0]=inter, [1]=pred_sum, [2]=target_sum
// zero-initialized at module load; finalize_kernel self-resets it each run
// via atomicExch, so no zeroing kernel is needed.
__device__ int g_counts[C_CLASSES * 3];

__global__ __launch_bounds__(THREADS) void count_kernel(
    const float* __restrict__ preds, const float* __restrict__ target) {
    int chunk = blockIdx.x / BLOCKS_PER_CHUNK;   // which (b,c)
    int sub   = blockIdx.x % BLOCKS_PER_CHUNK;
    int cls   = chunk % C_CLASSES;

    const float4* p = reinterpret_cast<const float4*>(preds)  + (size_t)chunk * HW4;
    const float4* t = reinterpret_cast<const float4*>(target) + (size_t)chunk * HW4;

    int base = sub * F4_PER_BLOCK + threadIdx.x;

    int inter = 0, ps = 0, ts = 0;
#pragma unroll
    for (int i = 0; i < F4_PER_THREAD; i++) {
        int idx = base + i * THREADS;
        float4 pv = p[idx];
        float4 tv = t[idx];
        int pm, tm;
        pm = pv.x >= 0.5f; tm = tv.x == 1.0f; ps += pm; ts += tm; inter += pm & tm;
        pm = pv.y >= 0.5f; tm = tv.y == 1.0f; ps += pm; ts += tm; inter += pm & tm;
        pm = pv.z >= 0.5f; tm = tv.z == 1.0f; ps += pm; ts += tm; inter += pm & tm;
        pm = pv.w >= 0.5f; tm = tv.w == 1.0f; ps += pm; ts += tm; inter += pm & tm;
    }

    // warp reduction
#pragma unroll
    for (int off = 16; off > 0; off >>= 1) {
        inter += __shfl_down_sync(0xFFFFFFFFu, inter, off);
        ps    += __shfl_down_sync(0xFFFFFFFFu, ps, off);
        ts    += __shfl_down_sync(0xFFFFFFFFu, ts, off);
    }

    __shared__ int s_inter[THREADS / 32];
    __shared__ int s_ps[THREADS / 32];
    __shared__ int s_ts[THREADS / 32];
    int lane = threadIdx.x & 31;
    int wid  = threadIdx.x >> 5;
    if (lane == 0) { s_inter[wid] = inter; s_ps[wid] = ps; s_ts[wid] = ts; }
    __syncthreads();

    if (threadIdx.x == 0) {
        int bi = 0, bp = 0, bt = 0;
#pragma unroll
        for (int w = 0; w < THREADS / 32; w++) { bi += s_inter[w]; bp += s_ps[w]; bt += s_ts[w]; }
        atomicAdd(&g_counts[cls * 3 + 0], bi);
        atomicAdd(&g_counts[cls * 3 + 1], bp);
        atomicAdd(&g_counts[cls * 3 + 2], bt);
    }
}

__global__ void finalize_kernel(float* __restrict__ out) {
    int c = threadIdx.x;
    if (c < C_CLASSES) {
        // atomicExch: coherent read + reset-to-zero for the next graph replay
        float inter = (float)atomicExch(&g_counts[c * 3 + 0], 0);
        float ps    = (float)atomicExch(&g_counts[c * 3 + 1], 0);
        float ts    = (float)atomicExch(&g_counts[c * 3 + 2], 0);
        float uni   = ps + ts - inter;
        float iou   = inter / fmaxf(uni, 1.0f);
        out[c] = (uni == 0.0f) ? nanf("") : iou;
    }
}

extern "C" void kernel_launch(void* const* d_in, const int* in_sizes, int n_in,
                              void* d_out, int out_size) {
    const float* preds  = (const float*)d_in[0];
    const float* target = (const float*)d_in[1];
    float* out = (float*)d_out;

    count_kernel<<<NCHUNKS * BLOCKS_PER_CHUNK, THREADS>>>(preds, target);
    finalize_kernel<<<1, 32>>>(out);
}